// round 1
// baseline (speedup 1.0000x reference)
#include <cuda_runtime.h>
#include <math.h>

#define TT 128
#define BB 512
#define HH 256
#define MM 64

// Scratch (device globals; no allocation allowed)
__device__ float g_memory[(size_t)MM * BB * HH];        // 32 MB recurrent state
__device__ float g_sentW[(size_t)TT * BB * HH];          // 64 MB: stories @ W, all steps
__device__ float g_keycand[MM * HH];                     // keys @ V

#define SA_STRIDE 257
#define SB_STRIDE 260
#define SA_FLOATS (64 * SA_STRIDE)        // 16448
#define SB_FLOATS (32 * SB_STRIDE)        // 8320
#define SMEM_FLOATS (SA_FLOATS + SB_FLOATS + 256 + 64)
#define SMEM_BYTES (SMEM_FLOATS * 4)      // 100352 bytes -> 2 CTAs/SM

// ---------------------------------------------------------------------------
// init: memory[m,b,h] = keys[m,h]
// ---------------------------------------------------------------------------
__global__ void init_mem_kernel(const float* __restrict__ keys) {
    int stride = gridDim.x * blockDim.x;
    for (int idx = blockIdx.x * blockDim.x + threadIdx.x; idx < MM * BB * HH; idx += stride) {
        int h = idx & (HH - 1);
        int m = idx >> 17;                 // / (BB*HH) = / 131072
        g_memory[idx] = keys[m * HH + h];
    }
}

// ---------------------------------------------------------------------------
// Generic C[R,256] = A[R,256] @ Bm[256,256], 64 rows per block.
// dst_sel: 0 -> g_sentW, 1 -> g_keycand
// ---------------------------------------------------------------------------
__global__ __launch_bounds__(256) void gemm64_kernel(const float* __restrict__ A,
                                                     const float* __restrict__ Bm,
                                                     int dst_sel) {
    extern __shared__ float sh[];
    float* sA = sh;                        // [64][257]
    float* sB = sh + SA_FLOATS;            // [32][260]
    float* __restrict__ C = dst_sel ? g_keycand : g_sentW;

    const int tid = threadIdx.x;
    const int tx = tid & 15, ty = tid >> 4;
    const size_t row0 = (size_t)blockIdx.x * 64;

    for (int idx = tid; idx < 64 * 256; idx += 256) {
        int r = idx >> 8, c = idx & 255;
        sA[r * SA_STRIDE + c] = A[(row0 + r) * HH + c];
    }

    float4 acc[4][4];
#pragma unroll
    for (int i = 0; i < 4; i++)
#pragma unroll
        for (int j = 0; j < 4; j++) acc[i][j] = make_float4(0.f, 0.f, 0.f, 0.f);

    for (int kt = 0; kt < 256; kt += 32) {
        __syncthreads();                    // prev compute done (and A-load on first iter)
        for (int idx = tid; idx < 32 * 256; idx += 256) {
            int r = idx >> 8, c = idx & 255;
            sB[r * SB_STRIDE + c] = Bm[(size_t)(kt + r) * HH + c];
        }
        __syncthreads();
#pragma unroll
        for (int kk = 0; kk < 32; kk++) {
            float a0 = sA[(ty     ) * SA_STRIDE + kt + kk];
            float a1 = sA[(ty + 16) * SA_STRIDE + kt + kk];
            float a2 = sA[(ty + 32) * SA_STRIDE + kt + kk];
            float a3 = sA[(ty + 48) * SA_STRIDE + kt + kk];
#pragma unroll
            for (int j = 0; j < 4; j++) {
                float4 bv = *(const float4*)(sB + kk * SB_STRIDE + (tx + 16 * j) * 4);
                acc[0][j].x += a0 * bv.x; acc[0][j].y += a0 * bv.y; acc[0][j].z += a0 * bv.z; acc[0][j].w += a0 * bv.w;
                acc[1][j].x += a1 * bv.x; acc[1][j].y += a1 * bv.y; acc[1][j].z += a1 * bv.z; acc[1][j].w += a1 * bv.w;
                acc[2][j].x += a2 * bv.x; acc[2][j].y += a2 * bv.y; acc[2][j].z += a2 * bv.z; acc[2][j].w += a2 * bv.w;
                acc[3][j].x += a3 * bv.x; acc[3][j].y += a3 * bv.y; acc[3][j].z += a3 * bv.z; acc[3][j].w += a3 * bv.w;
            }
        }
    }
#pragma unroll
    for (int i = 0; i < 4; i++)
#pragma unroll
        for (int j = 0; j < 4; j++)
            *(float4*)(C + (row0 + ty + 16 * i) * HH + (tx + 16 * j) * 4) = acc[i][j];
}

// ---------------------------------------------------------------------------
// One recurrence step. Block = (m = blockIdx.y, 64 b-rows at blockIdx.x*64).
//   gate  = sigmoid( dot(mem+keys[m], sent) )          [per row]
//   cand  = prelu( mem @ U + keycand[m] + sentW[t,b] )
//   mem   = normalize( mem + gate*mask*cand )
// ---------------------------------------------------------------------------
__global__ __launch_bounds__(256) void step_kernel(const float* __restrict__ stories,
                                                   const float* __restrict__ mask,
                                                   const float* __restrict__ keys,
                                                   const float* __restrict__ U,
                                                   const float* __restrict__ prelu_a,
                                                   float* __restrict__ gates_out,
                                                   int t) {
    extern __shared__ float sh[];
    float* sA    = sh;                      // mem tile [64][257]
    float* sB    = sh + SA_FLOATS;          // U tile / sent staging [32][260]
    float* sKeys = sB + SB_FLOATS;          // [256]
    float* sGm   = sKeys + 256;             // [64] gate*mask per row

    const int tid = threadIdx.x;
    const int tx = tid & 15, ty = tid >> 4;
    const int m = blockIdx.y;
    const int b0 = blockIdx.x * 64;

    const float* __restrict__ sent = stories + (size_t)t * BB * HH;
    float* __restrict__ memrow = g_memory + ((size_t)m * BB + b0) * HH;

    // stage memory tile + keys row
    for (int idx = tid; idx < 64 * 256; idx += 256) {
        int r = idx >> 8, c = idx & 255;
        sA[r * SA_STRIDE + c] = memrow[(size_t)r * HH + c];
    }
    sKeys[tid] = keys[m * HH + tid];
    __syncthreads();

    // ---- gate phase: dot(mem+keys, sent) per row, sent staged 32 rows at a time ----
    {
        const int r32 = tid >> 3, q = tid & 7;
#pragma unroll
        for (int half = 0; half < 2; half++) {
            for (int idx = tid; idx < 32 * 256; idx += 256) {
                int r = idx >> 8, c = idx & 255;
                sB[r * SB_STRIDE + c] = sent[(size_t)(b0 + half * 32 + r) * HH + c];
            }
            __syncthreads();
            float p = 0.f;
#pragma unroll
            for (int i = 0; i < 32; i++) {
                int k = q * 32 + i;
                p += (sA[(half * 32 + r32) * SA_STRIDE + k] + sKeys[k]) * sB[r32 * SB_STRIDE + k];
            }
            p += __shfl_xor_sync(0xffffffffu, p, 1);
            p += __shfl_xor_sync(0xffffffffu, p, 2);
            p += __shfl_xor_sync(0xffffffffu, p, 4);
            if (q == 0) {
                int b = b0 + half * 32 + r32;
                float g = 1.0f / (1.0f + expf(-p));
                gates_out[((size_t)t * MM + m) * BB + b] = g;
                sGm[half * 32 + r32] = g * mask[t * BB + b];
            }
            __syncthreads();
        }
    }

    // ---- GEMM: acc = memtile @ U ----
    float4 acc[4][4];
#pragma unroll
    for (int i = 0; i < 4; i++)
#pragma unroll
        for (int j = 0; j < 4; j++) acc[i][j] = make_float4(0.f, 0.f, 0.f, 0.f);

    for (int kt = 0; kt < 256; kt += 32) {
        for (int idx = tid; idx < 32 * 256; idx += 256) {
            int r = idx >> 8, c = idx & 255;
            sB[r * SB_STRIDE + c] = U[(size_t)(kt + r) * HH + c];
        }
        __syncthreads();
#pragma unroll
        for (int kk = 0; kk < 32; kk++) {
            float a0 = sA[(ty     ) * SA_STRIDE + kt + kk];
            float a1 = sA[(ty + 16) * SA_STRIDE + kt + kk];
            float a2 = sA[(ty + 32) * SA_STRIDE + kt + kk];
            float a3 = sA[(ty + 48) * SA_STRIDE + kt + kk];
#pragma unroll
            for (int j = 0; j < 4; j++) {
                float4 bv = *(const float4*)(sB + kk * SB_STRIDE + (tx + 16 * j) * 4);
                acc[0][j].x += a0 * bv.x; acc[0][j].y += a0 * bv.y; acc[0][j].z += a0 * bv.z; acc[0][j].w += a0 * bv.w;
                acc[1][j].x += a1 * bv.x; acc[1][j].y += a1 * bv.y; acc[1][j].z += a1 * bv.z; acc[1][j].w += a1 * bv.w;
                acc[2][j].x += a2 * bv.x; acc[2][j].y += a2 * bv.y; acc[2][j].z += a2 * bv.z; acc[2][j].w += a2 * bv.w;
                acc[3][j].x += a3 * bv.x; acc[3][j].y += a3 * bv.y; acc[3][j].z += a3 * bv.z; acc[3][j].w += a3 * bv.w;
            }
        }
        __syncthreads();                    // compute done before next stage / epilogue reuse of sA
    }

    // ---- epilogue: cand = prelu(acc + keycand + sentW); update, normalize, store ----
    const float4* __restrict__ kc4 = ((const float4*)g_keycand) + m * 64;
    const float4* __restrict__ pa4 = (const float4*)prelu_a;
    const float4* __restrict__ sw4 = (const float4*)(g_sentW + ((size_t)t * BB + b0) * HH);

#pragma unroll
    for (int i = 0; i < 4; i++) {
        int r = ty + 16 * i;
        float gm = sGm[r];
        float ss = 0.f;
#pragma unroll
        for (int j = 0; j < 4; j++) {
            int cq = tx + 16 * j;
            float4 kc = kc4[cq];
            float4 sw = sw4[r * 64 + cq];
            float4 pa = pa4[cq];
            float4 v = acc[i][j];
            float* arow = sA + r * SA_STRIDE + cq * 4;

            float t0 = v.x + kc.x + sw.x; t0 = (t0 >= 0.f) ? t0 : pa.x * t0; t0 = arow[0] + gm * t0; ss += t0 * t0; arow[0] = t0;
            float t1 = v.y + kc.y + sw.y; t1 = (t1 >= 0.f) ? t1 : pa.y * t1; t1 = arow[1] + gm * t1; ss += t1 * t1; arow[1] = t1;
            float t2 = v.z + kc.z + sw.z; t2 = (t2 >= 0.f) ? t2 : pa.z * t2; t2 = arow[2] + gm * t2; ss += t2 * t2; arow[2] = t2;
            float t3 = v.w + kc.w + sw.w; t3 = (t3 >= 0.f) ? t3 : pa.w * t3; t3 = arow[3] + gm * t3; ss += t3 * t3; arow[3] = t3;
        }
        // row-norm reduction across the 16 tx lanes (aligned 16-lane group in warp)
        ss += __shfl_xor_sync(0xffffffffu, ss, 1);
        ss += __shfl_xor_sync(0xffffffffu, ss, 2);
        ss += __shfl_xor_sync(0xffffffffu, ss, 4);
        ss += __shfl_xor_sync(0xffffffffu, ss, 8);
        float scale = 1.0f / fmaxf(sqrtf(ss), 1e-12f);
#pragma unroll
        for (int j = 0; j < 4; j++) {
            int cq = tx + 16 * j;
            const float* arow = sA + r * SA_STRIDE + cq * 4;
            float4 o = make_float4(arow[0] * scale, arow[1] * scale, arow[2] * scale, arow[3] * scale);
            *(float4*)(memrow + (size_t)r * HH + cq * 4) = o;
        }
    }
}

// ---------------------------------------------------------------------------
// final memory -> d_out[0 : M*B*H]
// ---------------------------------------------------------------------------
__global__ void copy_out_kernel(float4* __restrict__ out) {
    const float4* __restrict__ src = (const float4*)g_memory;
    int n4 = MM * BB * HH / 4;
    int stride = gridDim.x * blockDim.x;
    for (int idx = blockIdx.x * blockDim.x + threadIdx.x; idx < n4; idx += stride)
        out[idx] = src[idx];
}

// ---------------------------------------------------------------------------
extern "C" void kernel_launch(void* const* d_in, const int* in_sizes, int n_in,
                              void* d_out, int out_size) {
    const float* stories = (const float*)d_in[0];
    const float* mask    = (const float*)d_in[1];
    const float* keys    = (const float*)d_in[2];
    const float* U       = (const float*)d_in[3];
    const float* W       = (const float*)d_in[4];
    const float* V       = (const float*)d_in[5];
    const float* prelu_a = (const float*)d_in[6];
    float* out = (float*)d_out;
    float* gates_out = out + (size_t)MM * BB * HH;

    cudaFuncSetAttribute(gemm64_kernel, cudaFuncAttributeMaxDynamicSharedMemorySize, SMEM_BYTES);
    cudaFuncSetAttribute(step_kernel,   cudaFuncAttributeMaxDynamicSharedMemorySize, SMEM_BYTES);

    // memory init
    init_mem_kernel<<<1024, 256>>>(keys);
    // precompute sentW for ALL timesteps: [T*B,256] @ W
    gemm64_kernel<<<(TT * BB) / 64, 256, SMEM_BYTES>>>(stories, W, 0);
    // loop-invariant keycand = keys @ V
    gemm64_kernel<<<1, 256, SMEM_BYTES>>>(keys, V, 1);

    dim3 grid(BB / 64, MM);
    for (int t = 0; t < TT; t++)
        step_kernel<<<grid, 256, SMEM_BYTES>>>(stories, mask, keys, U, prelu_a, gates_out, t);

    copy_out_kernel<<<2048, 256>>>((float4*)out);
}

// round 2
// speedup vs baseline: 1.8349x; 1.8349x over previous
#include <cuda_runtime.h>
#include <cuda_bf16.h>
#include <math.h>

#define TT 128
#define BB 512
#define HH 256
#define MM 64

// ---------------- device scratch (no allocation allowed) ----------------
__device__ float g_memory[(size_t)MM * BB * HH];          // 32 MB recurrent state (fp32)
__device__ float g_sentW[(size_t)TT * BB * HH];            // 64 MB: stories @ W
__device__ float g_keycand[MM * HH];                       // keys @ V
__device__ __nv_bfloat16 g_Uthi[HH * HH];                  // U^T hi  [n][k]
__device__ __nv_bfloat16 g_Utlo[HH * HH];                  // U^T lo
__device__ __nv_bfloat16 g_Wthi[HH * HH];                  // W^T hi
__device__ __nv_bfloat16 g_Wtlo[HH * HH];                  // W^T lo

// ---------------- smem geometry ----------------
// A: [128 rows][264 bf16]  (stride 264 bf16 = 132 b32 ≡ 4 mod 32 -> conflict-free ldmatrix)
#define SA_STR 264
#define SA_ELEMS (128 * SA_STR)            // 33792 bf16 per split
// B chunk: [256 n][72 bf16] (k-chunk 64 + pad 8; stride 72 bf16 = 36 b32 ≡ 4 mod 32)
#define SB_STR 72
#define SB_ELEMS (256 * SB_STR)            // 18432 bf16 per split

#define OFF_AHI 0
#define OFF_ALO (OFF_AHI + SA_ELEMS * 2)
#define OFF_BHI (OFF_ALO + SA_ELEMS * 2)
#define OFF_BLO (OFF_BHI + SB_ELEMS * 2)
#define OFF_F32 (OFF_BLO + SB_ELEMS * 2)   // float area: keys[256], kc[256], pa[256], gm[128], rs[512]
#define STEP_SMEM (OFF_F32 + (256 + 256 + 256 + 128 + 512) * 4)   // 214528
#define TCG_SMEM  (OFF_BLO + SB_ELEMS * 2)                         // 208896

// fp32 keycand gemm smem (kept from R1, single tiny launch)
#define G64_SA_STRIDE 257
#define G64_SB_STRIDE 260
#define G64_SA_FLOATS (64 * G64_SA_STRIDE)
#define G64_SB_FLOATS (32 * G64_SB_STRIDE)
#define G64_SMEM ((G64_SA_FLOATS + G64_SB_FLOATS) * 4)

// ---------------- PTX helpers ----------------
__device__ __forceinline__ unsigned smem_u32(const void* p) {
    return (unsigned)__cvta_generic_to_shared(p);
}
__device__ __forceinline__ void ldsm_x4(unsigned addr, unsigned& r0, unsigned& r1, unsigned& r2, unsigned& r3) {
    asm volatile("ldmatrix.sync.aligned.m8n8.x4.shared.b16 {%0,%1,%2,%3}, [%4];"
                 : "=r"(r0), "=r"(r1), "=r"(r2), "=r"(r3) : "r"(addr));
}
__device__ __forceinline__ void mma16816(float* c, const unsigned* a, unsigned b0, unsigned b1) {
    asm volatile("mma.sync.aligned.m16n8k16.row.col.f32.bf16.bf16.f32 "
                 "{%0,%1,%2,%3}, {%4,%5,%6,%7}, {%8,%9}, {%0,%1,%2,%3};"
                 : "+f"(c[0]), "+f"(c[1]), "+f"(c[2]), "+f"(c[3])
                 : "r"(a[0]), "r"(a[1]), "r"(a[2]), "r"(a[3]), "r"(b0), "r"(b1));
}
__device__ __forceinline__ unsigned pack2(__nv_bfloat16 a, __nv_bfloat16 b) {
    unsigned r;
    unsigned short ua = *reinterpret_cast<unsigned short*>(&a);
    unsigned short ub = *reinterpret_cast<unsigned short*>(&b);
    r = (unsigned)ua | ((unsigned)ub << 16);
    return r;
}
// split 8 fp32 -> 8 bf16 hi + 8 bf16 lo (packed as uint4 each)
__device__ __forceinline__ void split8(float4 v0, float4 v1, uint4& h, uint4& l) {
    float f[8] = {v0.x, v0.y, v0.z, v0.w, v1.x, v1.y, v1.z, v1.w};
    unsigned hh[4], ll[4];
#pragma unroll
    for (int j = 0; j < 4; j++) {
        float a = f[2 * j], b = f[2 * j + 1];
        __nv_bfloat16 ha = __float2bfloat16(a), hb = __float2bfloat16(b);
        __nv_bfloat16 la = __float2bfloat16(a - __bfloat162float(ha));
        __nv_bfloat16 lb = __float2bfloat16(b - __bfloat162float(hb));
        hh[j] = pack2(ha, hb);
        ll[j] = pack2(la, lb);
    }
    h = make_uint4(hh[0], hh[1], hh[2], hh[3]);
    l = make_uint4(ll[0], ll[1], ll[2], ll[3]);
}

// ---------------- small prep kernels ----------------
__global__ void init_mem_kernel(const float* __restrict__ keys) {
    int stride = gridDim.x * blockDim.x;
    for (int idx = blockIdx.x * blockDim.x + threadIdx.x; idx < MM * BB * HH; idx += stride) {
        int h = idx & (HH - 1);
        int m = idx >> 17;
        g_memory[idx] = keys[m * HH + h];
    }
}

// dst[n][k] = split(src[k][n])   (transpose + hi/lo split)
__global__ void split_transpose_kernel(const float* __restrict__ src,
                                       __nv_bfloat16* __restrict__ hi,
                                       __nv_bfloat16* __restrict__ lo) {
    int idx = blockIdx.x * 256 + threadIdx.x;   // grid 256 -> 65536
    int n = idx >> 8, k = idx & 255;
    float x = src[k * 256 + n];
    __nv_bfloat16 h = __float2bfloat16(x);
    hi[idx] = h;
    lo[idx] = __float2bfloat16(x - __bfloat162float(h));
}

// fp32 gemm for tiny keycand (64x256 @ 256x256), 1 CTA — from R1
__global__ __launch_bounds__(256) void gemm64_kernel(const float* __restrict__ A,
                                                     const float* __restrict__ Bm) {
    extern __shared__ float sh[];
    float* sA = sh;
    float* sB = sh + G64_SA_FLOATS;
    const int tid = threadIdx.x;
    const int tx = tid & 15, ty = tid >> 4;

    for (int idx = tid; idx < 64 * 256; idx += 256) {
        int r = idx >> 8, c = idx & 255;
        sA[r * G64_SA_STRIDE + c] = A[r * HH + c];
    }
    float4 acc[4][4];
#pragma unroll
    for (int i = 0; i < 4; i++)
#pragma unroll
        for (int j = 0; j < 4; j++) acc[i][j] = make_float4(0.f, 0.f, 0.f, 0.f);

    for (int kt = 0; kt < 256; kt += 32) {
        __syncthreads();
        for (int idx = tid; idx < 32 * 256; idx += 256) {
            int r = idx >> 8, c = idx & 255;
            sB[r * G64_SB_STRIDE + c] = Bm[(kt + r) * HH + c];
        }
        __syncthreads();
#pragma unroll
        for (int kk = 0; kk < 32; kk++) {
            float a0 = sA[(ty) * G64_SA_STRIDE + kt + kk];
            float a1 = sA[(ty + 16) * G64_SA_STRIDE + kt + kk];
            float a2 = sA[(ty + 32) * G64_SA_STRIDE + kt + kk];
            float a3 = sA[(ty + 48) * G64_SA_STRIDE + kt + kk];
#pragma unroll
            for (int j = 0; j < 4; j++) {
                float4 bv = *(const float4*)(sB + kk * G64_SB_STRIDE + (tx + 16 * j) * 4);
                acc[0][j].x += a0 * bv.x; acc[0][j].y += a0 * bv.y; acc[0][j].z += a0 * bv.z; acc[0][j].w += a0 * bv.w;
                acc[1][j].x += a1 * bv.x; acc[1][j].y += a1 * bv.y; acc[1][j].z += a1 * bv.z; acc[1][j].w += a1 * bv.w;
                acc[2][j].x += a2 * bv.x; acc[2][j].y += a2 * bv.y; acc[2][j].z += a2 * bv.z; acc[2][j].w += a2 * bv.w;
                acc[3][j].x += a3 * bv.x; acc[3][j].y += a3 * bv.y; acc[3][j].z += a3 * bv.z; acc[3][j].w += a3 * bv.w;
            }
        }
    }
#pragma unroll
    for (int i = 0; i < 4; i++)
#pragma unroll
        for (int j = 0; j < 4; j++)
            *(float4*)(g_keycand + (ty + 16 * i) * HH + (tx + 16 * j) * 4) = acc[i][j];
}

// ---------------- shared mma core pieces ----------------
// stage A: 128 rows x 256 k of fp32 -> smem bf16 hi/lo
__device__ __forceinline__ void stage_A(const float* __restrict__ Asrc,
                                        __nv_bfloat16* sAhi, __nv_bfloat16* sAlo, int tid) {
    for (int i = tid; i < 128 * 32; i += 512) {
        int row = i >> 5, kq = (i & 31) << 3;
        const float* p = Asrc + row * 256 + kq;
        float4 v0 = *(const float4*)p;
        float4 v1 = *(const float4*)(p + 4);
        uint4 h, l;
        split8(v0, v1, h, l);
        *(uint4*)(sAhi + row * SA_STR + kq) = h;
        *(uint4*)(sAlo + row * SA_STR + kq) = l;
    }
}
// stage B chunk: g_Xt[n][kt..kt+63] -> sB[n][0..63]
__device__ __forceinline__ void stage_B(const __nv_bfloat16* __restrict__ Bthi,
                                        const __nv_bfloat16* __restrict__ Btlo,
                                        __nv_bfloat16* sBhi, __nv_bfloat16* sBlo,
                                        int kt, int tid) {
    for (int i = tid; i < 2048; i += 512) {
        int n = i >> 3, g = (i & 7) << 3;
        *(uint4*)(sBhi + n * SB_STR + g) = *(const uint4*)(Bthi + n * 256 + kt + g);
        *(uint4*)(sBlo + n * SB_STR + g) = *(const uint4*)(Btlo + n * 256 + kt + g);
    }
}

// the 128x256x256 bf16-split mma core: acc[2][8][4] per thread
#define MMA_CORE(sAhiU, sAloU, sBhiU, sBloU, rb, wc_, a_lr, a_lc, b_nr, b_kc, c_)           \
    {                                                                                        \
        _Pragma("unroll")                                                                    \
        for (int ks = 0; ks < 4; ks++) {                                                     \
            int kA = (c_) * 64 + ks * 16;                                                    \
            unsigned Ah[2][4], Al[2][4];                                                     \
            _Pragma("unroll")                                                                \
            for (int mi = 0; mi < 2; mi++) {                                                 \
                unsigned aoff = (unsigned)(((rb) + mi * 16 + (a_lr)) * SA_STR + kA + (a_lc)) * 2; \
                ldsm_x4(sAhiU + aoff, Ah[mi][0], Ah[mi][1], Ah[mi][2], Ah[mi][3]);           \
                ldsm_x4(sAloU + aoff, Al[mi][0], Al[mi][1], Al[mi][2], Al[mi][3]);           \
            }                                                                                \
            _Pragma("unroll")                                                                \
            for (int np = 0; np < 4; np++) {                                                 \
                int nb = (wc_) * 64 + np * 16;                                               \
                unsigned boff = (unsigned)((nb + (b_nr)) * SB_STR + ks * 16 + (b_kc)) * 2;   \
                unsigned Bh[4], Bl[4];                                                       \
                ldsm_x4(sBhiU + boff, Bh[0], Bh[1], Bh[2], Bh[3]);                           \
                ldsm_x4(sBloU + boff, Bl[0], Bl[1], Bl[2], Bl[3]);                           \
                _Pragma("unroll")                                                            \
                for (int mi = 0; mi < 2; mi++) {                                             \
                    _Pragma("unroll")                                                        \
                    for (int nj = 0; nj < 2; nj++) {                                         \
                        float* cc = acc[mi][np * 2 + nj];                                    \
                        mma16816(cc, Ah[mi], Bh[2 * nj], Bh[2 * nj + 1]);                    \
                        mma16816(cc, Ah[mi], Bl[2 * nj], Bl[2 * nj + 1]);                    \
                        mma16816(cc, Al[mi], Bh[2 * nj], Bh[2 * nj + 1]);                    \
                    }                                                                        \
                }                                                                            \
            }                                                                                \
        }                                                                                    \
    }

// ---------------- tc_gemm: C[row0+128][256] = A @ (Bt^T), plain store ----------------
__global__ __launch_bounds__(512, 1) void tc_gemm_kernel(const float* __restrict__ Asrc,
                                                         const __nv_bfloat16* __restrict__ Bthi,
                                                         const __nv_bfloat16* __restrict__ Btlo,
                                                         float* __restrict__ Cout) {
    extern __shared__ char sm[];
    __nv_bfloat16* sAhi = (__nv_bfloat16*)(sm + OFF_AHI);
    __nv_bfloat16* sAlo = (__nv_bfloat16*)(sm + OFF_ALO);
    __nv_bfloat16* sBhi = (__nv_bfloat16*)(sm + OFF_BHI);
    __nv_bfloat16* sBlo = (__nv_bfloat16*)(sm + OFF_BLO);

    const int tid = threadIdx.x;
    const int lane = tid & 31, wid = tid >> 5;
    const int wr = wid >> 2, wc = wid & 3;
    const int rb = wr * 32;
    const size_t row0 = (size_t)blockIdx.x * 128;

    const int a_lr = ((lane >> 3) & 1) * 8 + (lane & 7);
    const int a_lc = ((lane >> 4) & 1) * 8;
    const int b_nr = ((lane >> 4) << 3) + (lane & 7);
    const int b_kc = ((lane >> 3) & 1) << 3;

    const unsigned sAhiU = smem_u32(sAhi), sAloU = smem_u32(sAlo);
    const unsigned sBhiU = smem_u32(sBhi), sBloU = smem_u32(sBlo);

    stage_A(Asrc + row0 * 256, sAhi, sAlo, tid);

    float acc[2][8][4];
#pragma unroll
    for (int i = 0; i < 2; i++)
#pragma unroll
        for (int j = 0; j < 8; j++)
#pragma unroll
            for (int q = 0; q < 4; q++) acc[i][j][q] = 0.f;

    for (int c = 0; c < 4; c++) {
        __syncthreads();
        stage_B(Bthi, Btlo, sBhi, sBlo, c * 64, tid);
        __syncthreads();
        MMA_CORE(sAhiU, sAloU, sBhiU, sBloU, rb, wc, a_lr, a_lc, b_nr, b_kc, c)
    }

    const int gid = lane >> 2, tig = lane & 3;
#pragma unroll
    for (int mi = 0; mi < 2; mi++) {
        int r0 = rb + mi * 16 + gid, r1 = r0 + 8;
#pragma unroll
        for (int nt = 0; nt < 8; nt++) {
            int C = wc * 64 + nt * 8 + tig * 2;
            float* cc = acc[mi][nt];
            *(float2*)(Cout + (row0 + r0) * 256 + C) = make_float2(cc[0], cc[1]);
            *(float2*)(Cout + (row0 + r1) * 256 + C) = make_float2(cc[2], cc[3]);
        }
    }
}

// ---------------- the recurrence step ----------------
__global__ __launch_bounds__(512, 1) void step_tc_kernel(const float* __restrict__ stories,
                                                         const float* __restrict__ mask,
                                                         const float* __restrict__ keys,
                                                         const float* __restrict__ prelu_a,
                                                         float* __restrict__ gates_out,
                                                         int t) {
    extern __shared__ char sm[];
    __nv_bfloat16* sAhi = (__nv_bfloat16*)(sm + OFF_AHI);
    __nv_bfloat16* sAlo = (__nv_bfloat16*)(sm + OFF_ALO);
    __nv_bfloat16* sBhi = (__nv_bfloat16*)(sm + OFF_BHI);
    __nv_bfloat16* sBlo = (__nv_bfloat16*)(sm + OFF_BLO);
    float* sKeys = (float*)(sm + OFF_F32);           // [256]
    float* sKC   = sKeys + 256;                      // [256]
    float* sPA   = sKC + 256;                        // [256]
    float* sGm   = sPA + 256;                        // [128]
    float* sRS   = sGm + 128;                        // [128][4]

    const int tid = threadIdx.x;
    const int lane = tid & 31, wid = tid >> 5;
    const int wr = wid >> 2, wc = wid & 3;
    const int rb = wr * 32;
    const int m = blockIdx.y;
    const int b0 = blockIdx.x * 128;

    const float* __restrict__ sent = stories + (size_t)t * BB * HH;
    float* __restrict__ memrow = g_memory + ((size_t)m * BB + b0) * HH;

    if (tid < 256) {
        sKeys[tid] = keys[m * HH + tid];
        sKC[tid]   = g_keycand[m * HH + tid];
        sPA[tid]   = prelu_a[tid];
    }

    // stage memory tile as bf16 hi/lo
    stage_A(memrow, sAhi, sAlo, tid);
    __syncthreads();

    // ---- gate: sigmoid(dot(mem_row + keys, sent_row)) ----
    {
        int gr = tid >> 2, gq = tid & 3;
        const float* mrow = memrow + (size_t)gr * 256 + gq * 64;
        const float* srow = sent + (size_t)(b0 + gr) * 256 + gq * 64;
        const float* krow = sKeys + gq * 64;
        float p = 0.f;
#pragma unroll
        for (int kk = 0; kk < 64; kk += 4) {
            float4 a = *(const float4*)(mrow + kk);
            float4 s = *(const float4*)(srow + kk);
            float4 kv = *(const float4*)(krow + kk);
            p += (a.x + kv.x) * s.x + (a.y + kv.y) * s.y + (a.z + kv.z) * s.z + (a.w + kv.w) * s.w;
        }
        p += __shfl_xor_sync(0xffffffffu, p, 1);
        p += __shfl_xor_sync(0xffffffffu, p, 2);
        if (gq == 0) {
            float g = 1.0f / (1.0f + expf(-p));
            gates_out[((size_t)t * MM + m) * BB + b0 + gr] = g;
            sGm[gr] = g * mask[t * BB + b0 + gr];
        }
    }

    // ---- mma: acc = memtile @ U  (bf16 hi/lo 3-way split) ----
    const int a_lr = ((lane >> 3) & 1) * 8 + (lane & 7);
    const int a_lc = ((lane >> 4) & 1) * 8;
    const int b_nr = ((lane >> 4) << 3) + (lane & 7);
    const int b_kc = ((lane >> 3) & 1) << 3;
    const unsigned sAhiU = smem_u32(sAhi), sAloU = smem_u32(sAlo);
    const unsigned sBhiU = smem_u32(sBhi), sBloU = smem_u32(sBlo);

    float acc[2][8][4];
#pragma unroll
    for (int i = 0; i < 2; i++)
#pragma unroll
        for (int j = 0; j < 8; j++)
#pragma unroll
            for (int q = 0; q < 4; q++) acc[i][j][q] = 0.f;

    for (int c = 0; c < 4; c++) {
        __syncthreads();
        stage_B(g_Uthi, g_Utlo, sBhi, sBlo, c * 64, tid);
        __syncthreads();
        MMA_CORE(sAhiU, sAloU, sBhiU, sBloU, rb, wc, a_lr, a_lc, b_nr, b_kc, c)
    }

    // ---- epilogue: cand=prelu(acc+kc+sw); mem'=normalize(mem + g*m*cand) ----
    const int gid = lane >> 2, tig = lane & 3;
    const float* __restrict__ swbase = g_sentW + ((size_t)t * BB + b0) * HH;

#pragma unroll
    for (int mi = 0; mi < 2; mi++) {
        int r0 = rb + mi * 16 + gid, r1 = r0 + 8;
        float gm0 = sGm[r0], gm1 = sGm[r1];
        float ss0 = 0.f, ss1 = 0.f;
#pragma unroll
        for (int nt = 0; nt < 8; nt++) {
            int C = wc * 64 + nt * 8 + tig * 2;
            float2 kc = *(const float2*)(sKC + C);
            float2 pa = *(const float2*)(sPA + C);
            float2 sw0 = *(const float2*)(swbase + (size_t)r0 * 256 + C);
            float2 sw1 = *(const float2*)(swbase + (size_t)r1 * 256 + C);
            float2 om0 = *(const float2*)(memrow + (size_t)r0 * 256 + C);
            float2 om1 = *(const float2*)(memrow + (size_t)r1 * 256 + C);
            float* cc = acc[mi][nt];
            float v;
            v = cc[0] + kc.x + sw0.x; v = (v >= 0.f) ? v : pa.x * v; v = om0.x + gm0 * v; ss0 += v * v; cc[0] = v;
            v = cc[1] + kc.y + sw0.y; v = (v >= 0.f) ? v : pa.y * v; v = om0.y + gm0 * v; ss0 += v * v; cc[1] = v;
            v = cc[2] + kc.x + sw1.x; v = (v >= 0.f) ? v : pa.x * v; v = om1.x + gm1 * v; ss1 += v * v; cc[2] = v;
            v = cc[3] + kc.y + sw1.y; v = (v >= 0.f) ? v : pa.y * v; v = om1.y + gm1 * v; ss1 += v * v; cc[3] = v;
        }
        ss0 += __shfl_xor_sync(0xffffffffu, ss0, 1);
        ss0 += __shfl_xor_sync(0xffffffffu, ss0, 2);
        ss1 += __shfl_xor_sync(0xffffffffu, ss1, 1);
        ss1 += __shfl_xor_sync(0xffffffffu, ss1, 2);
        if (tig == 0) {
            sRS[r0 * 4 + wc] = ss0;
            sRS[r1 * 4 + wc] = ss1;
        }
    }
    __syncthreads();

#pragma unroll
    for (int mi = 0; mi < 2; mi++) {
        int r0 = rb + mi * 16 + gid, r1 = r0 + 8;
        float s0 = sRS[r0 * 4 + 0] + sRS[r0 * 4 + 1] + sRS[r0 * 4 + 2] + sRS[r0 * 4 + 3];
        float s1 = sRS[r1 * 4 + 0] + sRS[r1 * 4 + 1] + sRS[r1 * 4 + 2] + sRS[r1 * 4 + 3];
        float sc0 = 1.0f / fmaxf(sqrtf(s0), 1e-12f);
        float sc1 = 1.0f / fmaxf(sqrtf(s1), 1e-12f);
#pragma unroll
        for (int nt = 0; nt < 8; nt++) {
            int C = wc * 64 + nt * 8 + tig * 2;
            float* cc = acc[mi][nt];
            *(float2*)(memrow + (size_t)r0 * 256 + C) = make_float2(cc[0] * sc0, cc[1] * sc0);
            *(float2*)(memrow + (size_t)r1 * 256 + C) = make_float2(cc[2] * sc1, cc[3] * sc1);
        }
    }
}

// ---------------- output ----------------
__global__ void copy_out_kernel(float4* __restrict__ out) {
    const float4* __restrict__ src = (const float4*)g_memory;
    int n4 = MM * BB * HH / 4;
    int stride = gridDim.x * blockDim.x;
    for (int idx = blockIdx.x * blockDim.x + threadIdx.x; idx < n4; idx += stride)
        out[idx] = src[idx];
}

// ---------------------------------------------------------------------------
extern "C" void kernel_launch(void* const* d_in, const int* in_sizes, int n_in,
                              void* d_out, int out_size) {
    const float* stories = (const float*)d_in[0];
    const float* mask    = (const float*)d_in[1];
    const float* keys    = (const float*)d_in[2];
    const float* U       = (const float*)d_in[3];
    const float* W       = (const float*)d_in[4];
    const float* V       = (const float*)d_in[5];
    const float* prelu_a = (const float*)d_in[6];
    float* out = (float*)d_out;
    float* gates_out = out + (size_t)MM * BB * HH;

    static bool attr_done = false;
    if (!attr_done) {
        cudaFuncSetAttribute(gemm64_kernel,  cudaFuncAttributeMaxDynamicSharedMemorySize, G64_SMEM);
        cudaFuncSetAttribute(tc_gemm_kernel, cudaFuncAttributeMaxDynamicSharedMemorySize, TCG_SMEM);
        cudaFuncSetAttribute(step_tc_kernel, cudaFuncAttributeMaxDynamicSharedMemorySize, STEP_SMEM);
        attr_done = true;
    }

    __nv_bfloat16 *uthi, *utlo, *wthi, *wtlo;
    cudaGetSymbolAddress((void**)&uthi, g_Uthi);
    cudaGetSymbolAddress((void**)&utlo, g_Utlo);
    cudaGetSymbolAddress((void**)&wthi, g_Wthi);
    cudaGetSymbolAddress((void**)&wtlo, g_Wtlo);

    // prep
    split_transpose_kernel<<<256, 256>>>(U, uthi, utlo);
    split_transpose_kernel<<<256, 256>>>(W, wthi, wtlo);
    init_mem_kernel<<<1024, 256>>>(keys);
    gemm64_kernel<<<1, 256, G64_SMEM>>>(keys, V);                       // keycand (fp32, tiny)

    float* sentw;
    cudaGetSymbolAddress((void**)&sentw, g_sentW);
    tc_gemm_kernel<<<(TT * BB) / 128, 512, TCG_SMEM>>>(stories, wthi, wtlo, sentw);

    // recurrence
    dim3 grid(BB / 128, MM);
    for (int t = 0; t < TT; t++)
        step_tc_kernel<<<grid, 512, STEP_SMEM>>>(stories, mask, keys, prelu_a, gates_out, t);

    copy_out_kernel<<<2048, 256>>>((float4*)out);
}